// round 6
// baseline (speedup 1.0000x reference)
#include <cuda_runtime.h>
#include <cuda_bf16.h>
#include <math.h>
#include <stdint.h>

#define MROWS (4 * 8192)          // 32768 rows total
#define DIMK  512
#define NQKV  1536

// ---------------- scratch (device globals; no allocation allowed) ----------
__device__ float g_q[MROWS * 512];          // elu(q)+1 fp32
__device__ float g_k[MROWS * 512];          // elu(k)+1 fp32
__device__ float g_v[MROWS * 512];          // v fp32
__device__ float g_kvpart[32 * 16 * 4160];  // per (bh,chunk): 64x64 kv + 64 ksum
__device__ float g_kv[32 * 4160];
__device__ float g_z[32 * 8192];
__device__ float g_wt[NQKV * 512];          // w_qkv^T fp32 [n][k]

__device__ __nv_bfloat16 g_xh[MROWS * 512];   // x hi/lo (same index as x)
__device__ __nv_bfloat16 g_xl[MROWS * 512];
__device__ __nv_bfloat16 g_wth[NQKV * 512];   // w^T hi/lo (same index as g_wt)
__device__ __nv_bfloat16 g_wtl[NQKV * 512];
__device__ __nv_bfloat16 g_qzh[MROWS * 512];  // (q*z) hi/lo (same index as g_q)
__device__ __nv_bfloat16 g_qzl[MROWS * 512];
__device__ __nv_bfloat16 g_wbth[4 * 512 * 512]; // Wbig^T hi/lo [b][j][r]
__device__ __nv_bfloat16 g_wbtl[4 * 512 * 512];

// ---------------- helpers ---------------------------------------------------
__device__ __forceinline__ void mma16816(float* c, const uint32_t* a, const uint32_t* b) {
    asm volatile(
        "mma.sync.aligned.m16n8k16.row.col.f32.bf16.bf16.f32 "
        "{%0,%1,%2,%3}, {%4,%5,%6,%7}, {%8,%9}, {%0,%1,%2,%3};"
        : "+f"(c[0]), "+f"(c[1]), "+f"(c[2]), "+f"(c[3])
        : "r"(a[0]), "r"(a[1]), "r"(a[2]), "r"(a[3]), "r"(b[0]), "r"(b[1]));
}

__device__ __forceinline__ float elu1(float x) {
    return x >= 0.f ? x + 1.f : __expf(x);
}
__device__ __forceinline__ void split2(float v, __nv_bfloat16& hi, __nv_bfloat16& lo) {
    hi = __float2bfloat16_rn(v);
    lo = __float2bfloat16_rn(v - __bfloat162float(hi));
}
__device__ __forceinline__ uint32_t lds32(const __nv_bfloat16* p) {
    return *(const uint32_t*)p;
}

// ============================================================================
// W transpose: g_wt[n][k] = W[k][n]   (W: [512][1536])   [R5-verified]
// ============================================================================
__global__ void transpose_w(const float* __restrict__ W)
{
    __shared__ float t[32][33];
    const int bx = blockIdx.x * 32;   // n base
    const int by = blockIdx.y * 32;   // k base
    const int x = threadIdx.x;
    for (int yy = threadIdx.y; yy < 32; yy += 8)
        t[yy][x] = W[(size_t)(by + yy) * NQKV + bx + x];
    __syncthreads();
    for (int yy = threadIdx.y; yy < 32; yy += 8)
        g_wt[(size_t)(bx + yy) * 512 + by + x] = t[x][yy];
}

// ============================================================================
// Same-index elementwise split: H[i]=hi(src[i]), L[i]=lo(src[i])
// ============================================================================
__global__ void conv_split(const float* __restrict__ src,
                           __nv_bfloat16* __restrict__ H,
                           __nv_bfloat16* __restrict__ L)
{
    size_t i4 = (size_t)blockIdx.x * 256 + threadIdx.x;
    float4 v = ((const float4*)src)[i4];
    __nv_bfloat16 h0, h1, h2, h3, l0, l1, l2, l3;
    split2(v.x, h0, l0); split2(v.y, h1, l1); split2(v.z, h2, l2); split2(v.w, h3, l3);
    ((__nv_bfloat162*)H)[i4 * 2]     = __nv_bfloat162(h0, h1);
    ((__nv_bfloat162*)H)[i4 * 2 + 1] = __nv_bfloat162(h2, h3);
    ((__nv_bfloat162*)L)[i4 * 2]     = __nv_bfloat162(l0, l1);
    ((__nv_bfloat162*)L)[i4 * 2 + 1] = __nv_bfloat162(l2, l3);
}

// ============================================================================
// conv_qz: same-index split of q[i]*z  (z index math identical to R5 gemm MODE1)
// ============================================================================
__global__ void conv_qz()
{
    size_t i4 = (size_t)blockIdx.x * 256 + threadIdx.x;
    size_t e = i4 * 4;
    int row = (int)(e >> 9);          // global row
    int c = (int)(e & 511);           // column; c..c+3 within one 64-wide head
    int b = row >> 13, n = row & 8191;
    float zv = g_z[(size_t)(b * 8 + (c >> 6)) * 8192 + n];
    float4 v = ((const float4*)g_q)[i4];
    v.x *= zv; v.y *= zv; v.z *= zv; v.w *= zv;
    __nv_bfloat16 h0, h1, h2, h3, l0, l1, l2, l3;
    split2(v.x, h0, l0); split2(v.y, h1, l1); split2(v.z, h2, l2); split2(v.w, h3, l3);
    ((__nv_bfloat162*)g_qzh)[i4 * 2]     = __nv_bfloat162(h0, h1);
    ((__nv_bfloat162*)g_qzh)[i4 * 2 + 1] = __nv_bfloat162(h2, h3);
    ((__nv_bfloat162*)g_qzl)[i4 * 2]     = __nv_bfloat162(l0, l1);
    ((__nv_bfloat162*)g_qzl)[i4 * 2 + 1] = __nv_bfloat162(l2, l3);
}

// ============================================================================
// bf16-split GEMM via mma.sync. C tile 128x128, K=512 in 16 chunks of 32.
// Pre-split bf16 sources; register double-buffered synchronous loads.
// Compute + epilogue byte-identical to R5-verified version.
// MODE 0: C = X @ W -> split q/k/v, elu+1 on q,k
// MODE 1: C = (q*z) @ Wbig + bias -> Out   (z pre-applied in conv_qz)
// ============================================================================
#define PITCH 40                      // bf16 per smem row (80 B) -> conflict-free frags

template <int MODE>
__global__ __launch_bounds__(256) void gemm_mma(
    const __nv_bfloat16* __restrict__ AH, const __nv_bfloat16* __restrict__ AL,
    const __nv_bfloat16* __restrict__ BHg, const __nv_bfloat16* __restrict__ BLg,
    const float* __restrict__ bias, float* __restrict__ Out)
{
    __shared__ __nv_bfloat16 sAh[128 * PITCH];
    __shared__ __nv_bfloat16 sAl[128 * PITCH];
    __shared__ __nv_bfloat16 sBh[128 * PITCH];
    __shared__ __nv_bfloat16 sBl[128 * PITCH];

    const int tid = threadIdx.x;
    const int wid = tid >> 5, lane = tid & 31;
    const int g = lane >> 2, tig = lane & 3;
    const int m0 = blockIdx.y * 128;
    const int n0 = blockIdx.x * 128;
    const int wm = (wid & 1) * 64;
    const int wn = (wid >> 1) * 32;
    const int bb = m0 >> 13;          // batch (tiles never straddle batches)

    const __nv_bfloat16* BH = BHg + (MODE == 1 ? (size_t)bb * 262144 : 0);
    const __nv_bfloat16* BL = BLg + (MODE == 1 ? (size_t)bb * 262144 : 0);

    // per-thread fill slots: idx = tid + 256*i (i<2); row = idx>>2, ch = idx&3
    const int fr0 = tid >> 2, fch0 = (tid & 3) * 8;
    const int fr1 = (tid + 256) >> 2, fch1 = ((tid + 256) & 3) * 8;

    float acc[4][4][4];
#pragma unroll
    for (int i = 0; i < 4; i++)
#pragma unroll
        for (int j = 0; j < 4; j++)
#pragma unroll
            for (int t = 0; t < 4; t++) acc[i][j][t] = 0.f;

    uint4 pah[2], pal[2], pbh[2], pbl[2];

    // ---- fetch chunk 0 into registers ----
    {
        const int k0 = 0;
        pah[0] = *(const uint4*)(AH + (size_t)(m0 + fr0) * 512 + k0 + fch0);
        pah[1] = *(const uint4*)(AH + (size_t)(m0 + fr1) * 512 + k0 + fch1);
        pal[0] = *(const uint4*)(AL + (size_t)(m0 + fr0) * 512 + k0 + fch0);
        pal[1] = *(const uint4*)(AL + (size_t)(m0 + fr1) * 512 + k0 + fch1);
        pbh[0] = *(const uint4*)(BH + (size_t)(n0 + fr0) * 512 + k0 + fch0);
        pbh[1] = *(const uint4*)(BH + (size_t)(n0 + fr1) * 512 + k0 + fch1);
        pbl[0] = *(const uint4*)(BL + (size_t)(n0 + fr0) * 512 + k0 + fch0);
        pbl[1] = *(const uint4*)(BL + (size_t)(n0 + fr1) * 512 + k0 + fch1);
    }

    for (int kc = 0; kc < 16; kc++) {
        // ---- store prefetched regs to smem ----
        *(uint4*)(sAh + fr0 * PITCH + fch0) = pah[0];
        *(uint4*)(sAh + fr1 * PITCH + fch1) = pah[1];
        *(uint4*)(sAl + fr0 * PITCH + fch0) = pal[0];
        *(uint4*)(sAl + fr1 * PITCH + fch1) = pal[1];
        *(uint4*)(sBh + fr0 * PITCH + fch0) = pbh[0];
        *(uint4*)(sBh + fr1 * PITCH + fch1) = pbh[1];
        *(uint4*)(sBl + fr0 * PITCH + fch0) = pbl[0];
        *(uint4*)(sBl + fr1 * PITCH + fch1) = pbl[1];
        __syncthreads();

        // ---- fetch next chunk into registers (overlaps with compute) ----
        if (kc < 15) {
            const int k0 = (kc + 1) * 32;
            pah[0] = *(const uint4*)(AH + (size_t)(m0 + fr0) * 512 + k0 + fch0);
            pah[1] = *(const uint4*)(AH + (size_t)(m0 + fr1) * 512 + k0 + fch1);
            pal[0] = *(const uint4*)(AL + (size_t)(m0 + fr0) * 512 + k0 + fch0);
            pal[1] = *(const uint4*)(AL + (size_t)(m0 + fr1) * 512 + k0 + fch1);
            pbh[0] = *(const uint4*)(BH + (size_t)(n0 + fr0) * 512 + k0 + fch0);
            pbh[1] = *(const uint4*)(BH + (size_t)(n0 + fr1) * 512 + k0 + fch1);
            pbl[0] = *(const uint4*)(BL + (size_t)(n0 + fr0) * 512 + k0 + fch0);
            pbl[1] = *(const uint4*)(BL + (size_t)(n0 + fr1) * 512 + k0 + fch1);
        }

        // ---- compute: 2 k-halves of 16, explicit fragment loads [R5-verified] ----
#pragma unroll
        for (int ks = 0; ks < 2; ks++) {
            const int ko = ks * 16 + tig * 2;
            uint32_t ah[4][4], al[4][4];
#pragma unroll
            for (int mt = 0; mt < 4; mt++) {
                const int r = wm + mt * 16 + g;
                ah[mt][0] = lds32(sAh + r * PITCH + ko);
                ah[mt][1] = lds32(sAh + (r + 8) * PITCH + ko);
                ah[mt][2] = lds32(sAh + r * PITCH + ko + 8);
                ah[mt][3] = lds32(sAh + (r + 8) * PITCH + ko + 8);
                al[mt][0] = lds32(sAl + r * PITCH + ko);
                al[mt][1] = lds32(sAl + (r + 8) * PITCH + ko);
                al[mt][2] = lds32(sAl + r * PITCH + ko + 8);
                al[mt][3] = lds32(sAl + (r + 8) * PITCH + ko + 8);
            }
            uint32_t bh[4][2], bl[4][2];
#pragma unroll
            for (int nt = 0; nt < 4; nt++) {
                const int rn = wn + nt * 8 + g;
                bh[nt][0] = lds32(sBh + rn * PITCH + ko);
                bh[nt][1] = lds32(sBh + rn * PITCH + ko + 8);
                bl[nt][0] = lds32(sBl + rn * PITCH + ko);
                bl[nt][1] = lds32(sBl + rn * PITCH + ko + 8);
            }
#pragma unroll
            for (int mt = 0; mt < 4; mt++)
#pragma unroll
                for (int nt = 0; nt < 4; nt++) {
                    mma16816(acc[mt][nt], ah[mt], bh[nt]);
                    mma16816(acc[mt][nt], ah[mt], bl[nt]);
                    mma16816(acc[mt][nt], al[mt], bh[nt]);
                }
        }
        __syncthreads();   // all reads done before next store phase
    }

    // -------- epilogue [R5-verified] --------
    if (MODE == 0) {
        float* dst = (n0 < 512) ? g_q : (n0 < 1024 ? g_k : g_v);
        const bool act = (n0 < 1024);
        const int cb = (n0 & 511) + wn;
#pragma unroll
        for (int mt = 0; mt < 4; mt++) {
            int r0 = m0 + wm + mt * 16 + g;
#pragma unroll
            for (int nt = 0; nt < 4; nt++) {
                int c = cb + nt * 8 + tig * 2;
                float v0 = acc[mt][nt][0], v1 = acc[mt][nt][1];
                float v2 = acc[mt][nt][2], v3 = acc[mt][nt][3];
                if (act) { v0 = elu1(v0); v1 = elu1(v1); v2 = elu1(v2); v3 = elu1(v3); }
                *(float2*)&dst[(size_t)r0 * 512 + c]       = make_float2(v0, v1);
                *(float2*)&dst[(size_t)(r0 + 8) * 512 + c] = make_float2(v2, v3);
            }
        }
    } else {
        const int cb = n0 + wn;
#pragma unroll
        for (int mt = 0; mt < 4; mt++) {
            int r0 = m0 + wm + mt * 16 + g;
#pragma unroll
            for (int nt = 0; nt < 4; nt++) {
                int c = cb + nt * 8 + tig * 2;
                float b0 = bias[c], b1 = bias[c + 1];
                *(float2*)&Out[(size_t)r0 * 512 + c] =
                    make_float2(acc[mt][nt][0] + b0, acc[mt][nt][1] + b1);
                *(float2*)&Out[(size_t)(r0 + 8) * 512 + c] =
                    make_float2(acc[mt][nt][2] + b0, acc[mt][nt][3] + b1);
            }
        }
    }
}

// ============================================================================
// kv partial reduce + combine (fp32 SIMT) [R1/R5-verified]
// ============================================================================
__global__ __launch_bounds__(256, 4) void kv_reduce()
{
    __shared__ float ks[8][64];
    __shared__ float vs[8][64];
    const int bh = blockIdx.x;
    const int b = bh >> 3, h = bh & 7;
    const int nbase = blockIdx.y * 512;
    const int tid = threadIdx.x;
    const int tx = tid & 15, ty = tid >> 4;

    float acc[4][4];
#pragma unroll
    for (int i = 0; i < 4; i++)
#pragma unroll
        for (int j = 0; j < 4; j++) acc[i][j] = 0.f;
    float ksacc[4] = {0.f, 0.f, 0.f, 0.f};

    const int lr = (tid & 127) >> 4;
    const int lc = tid & 15;
    const float* src = (tid < 128) ? g_k : g_v;
    float* sdst = (tid < 128) ? &ks[lr][lc * 4] : &vs[lr][lc * 4];

    for (int r0 = 0; r0 < 512; r0 += 8) {
        int n = nbase + r0 + lr;
        float4 val = *(const float4*)&src[((size_t)(b * 8192 + n)) * 512 + h * 64 + lc * 4];
        *(float4*)sdst = val;
        __syncthreads();
#pragma unroll
        for (int r = 0; r < 8; r++) {
            float kf[4], vf[4];
            *(float4*)kf = *(float4*)&ks[r][tx * 4];
            *(float4*)vf = *(float4*)&vs[r][ty * 4];
#pragma unroll
            for (int i = 0; i < 4; i++)
#pragma unroll
                for (int j = 0; j < 4; j++) acc[i][j] += kf[i] * vf[j];
            if (ty == 0) {
#pragma unroll
                for (int i = 0; i < 4; i++) ksacc[i] += kf[i];
            }
        }
        __syncthreads();
    }

    const size_t base = (size_t)(bh * 16 + blockIdx.y) * 4160;
#pragma unroll
    for (int i = 0; i < 4; i++)
#pragma unroll
        for (int j = 0; j < 4; j++)
            g_kvpart[base + (tx * 4 + i) * 64 + ty * 4 + j] = acc[i][j];
    if (ty == 0) {
#pragma unroll
        for (int i = 0; i < 4; i++) g_kvpart[base + 4096 + tx * 4 + i] = ksacc[i];
    }
}

__global__ void kv_combine()
{
    const int bh = blockIdx.x;
    const int i0 = blockIdx.y * 260;
    const int iend = (i0 + 260 < 4160) ? i0 + 260 : 4160;
    for (int i = i0 + threadIdx.x; i < iend; i += 256) {
        float s = 0.f;
#pragma unroll
        for (int c = 0; c < 16; c++) s += g_kvpart[(size_t)(bh * 16 + c) * 4160 + i];
        g_kv[(size_t)bh * 4160 + i] = s;
    }
}

// ============================================================================
// Wbig^T bf16 hi/lo: [b][j][r] = sum_m kv[b,h,d,m] * w_out[h*64+m][j], r=h*64+d
// (R5-verified compute; store converted to hi/lo at the end)
// ============================================================================
__global__ void make_wbig(const float* __restrict__ Wout)
{
    const int r = blockIdx.x;          // h*64+d
    const int b = blockIdx.y;
    const int h = r >> 6, d = r & 63;
    __shared__ float kvrow[64];
    if (threadIdx.x < 64)
        kvrow[threadIdx.x] = g_kv[(size_t)(b * 8 + h) * 4160 + d * 64 + threadIdx.x];
    __syncthreads();
    float acc[4] = {0.f, 0.f, 0.f, 0.f};
    for (int m = 0; m < 64; m++) {
        float kvv = kvrow[m];
        const float* wrow = Wout + (size_t)(h * 64 + m) * 512;
#pragma unroll
        for (int i = 0; i < 4; i++) acc[i] += kvv * wrow[threadIdx.x + i * 128];
    }
#pragma unroll
    for (int i = 0; i < 4; i++) {
        int j = threadIdx.x + i * 128;
        __nv_bfloat16 hi, lo;
        split2(acc[i], hi, lo);
        g_wbth[(size_t)b * 262144 + (size_t)j * 512 + r] = hi;
        g_wbtl[(size_t)b * 262144 + (size_t)j * 512 + r] = lo;
    }
}

// ============================================================================
// z = 1 / (q . ksum + 1e-6)    [R1/R5-verified]
// ============================================================================
__global__ void compute_z()
{
    const int idx = blockIdx.x * 512 + threadIdx.x;
    const int n = idx & 8191;
    const int bh = idx >> 13;
    const int b = bh >> 3, h = bh & 7;
    const float* qrow = g_q + (size_t)(b * 8192 + n) * 512 + h * 64;
    const float* ksum = g_kv + (size_t)bh * 4160 + 4096;
    float s = 0.f;
#pragma unroll
    for (int i = 0; i < 16; i++) {
        float4 qv = *(const float4*)(qrow + i * 4);
        float4 kv = *(const float4*)(ksum + i * 4);
        s += qv.x * kv.x + qv.y * kv.y + qv.z * kv.z + qv.w * kv.w;
    }
    g_z[idx] = 1.0f / (s + 1e-6f);
}

// ============================================================================
extern "C" void kernel_launch(void* const* d_in, const int* in_sizes, int n_in,
                              void* d_out, int out_size)
{
    const float* x     = (const float*)d_in[0];   // [4,8192,512]
    const float* w_qkv = (const float*)d_in[1];   // [512,1536]
    const float* w_out = (const float*)d_in[2];   // [512,512]
    const float* b_out = (const float*)d_in[3];   // [512]
    float* out = (float*)d_out;                   // [4,8192,512]

    float* wt_p;    cudaGetSymbolAddress((void**)&wt_p,  g_wt);
    __nv_bfloat16 *xh_p, *xl_p, *wth_p, *wtl_p, *qzh_p, *qzl_p, *wbth_p, *wbtl_p;
    cudaGetSymbolAddress((void**)&xh_p,  g_xh);
    cudaGetSymbolAddress((void**)&xl_p,  g_xl);
    cudaGetSymbolAddress((void**)&wth_p, g_wth);
    cudaGetSymbolAddress((void**)&wtl_p, g_wtl);
    cudaGetSymbolAddress((void**)&qzh_p, g_qzh);
    cudaGetSymbolAddress((void**)&qzl_p, g_qzl);
    cudaGetSymbolAddress((void**)&wbth_p, g_wbth);
    cudaGetSymbolAddress((void**)&wbtl_p, g_wbtl);

    transpose_w<<<dim3(48, 16), dim3(32, 8)>>>(w_qkv);
    conv_split<<<16384, 256>>>(x, xh_p, xl_p);                 // X: 16.7M elems
    conv_split<<<768, 256>>>(wt_p, wth_p, wtl_p);              // W^T: 0.79M elems
    gemm_mma<0><<<dim3(12, 256), 256>>>(xh_p, xl_p, wth_p, wtl_p, nullptr, nullptr);
    kv_reduce<<<dim3(32, 16), 256>>>();
    kv_combine<<<dim3(32, 16), 256>>>();
    make_wbig<<<dim3(512, 4), 128>>>(w_out);
    compute_z<<<512, 512>>>();
    conv_qz<<<16384, 256>>>();
    gemm_mma<1><<<dim3(4, 256), 256>>>(qzh_p, qzl_p, wbth_p, wbtl_p, b_out, out);
}

// round 7
// speedup vs baseline: 1.0733x; 1.0733x over previous
#include <cuda_runtime.h>
#include <cuda_bf16.h>
#include <math.h>
#include <stdint.h>

#define MROWS (4 * 8192)          // 32768 rows total
#define DIMK  512
#define NQKV  1536

// ---------------- scratch (device globals; no allocation allowed) ----------
__device__ float g_q[MROWS * 512];          // elu(q)+1 fp32
__device__ float g_k[MROWS * 512];          // elu(k)+1 fp32
__device__ float g_v[MROWS * 512];          // v fp32
__device__ float g_kvpart[32 * 16 * 4160];  // per (bh,chunk): 64x64 kv + 64 ksum
__device__ float g_kv[32 * 4160];
__device__ float g_z[32 * 8192];
__device__ float g_wt[NQKV * 512];          // w_qkv^T fp32 [n][k]

__device__ __nv_bfloat16 g_xh[MROWS * 512];   // x hi/lo (same index as x)
__device__ __nv_bfloat16 g_xl[MROWS * 512];
__device__ __nv_bfloat16 g_wth[NQKV * 512];   // w^T hi/lo (same index as g_wt)
__device__ __nv_bfloat16 g_wtl[NQKV * 512];
__device__ __nv_bfloat16 g_qzh[MROWS * 512];  // (q*z) hi/lo (same index as g_q)
__device__ __nv_bfloat16 g_qzl[MROWS * 512];
__device__ __nv_bfloat16 g_wbth[4 * 512 * 512]; // Wbig^T hi/lo [b][j][r]
__device__ __nv_bfloat16 g_wbtl[4 * 512 * 512];

// ---------------- helpers ---------------------------------------------------
__device__ __forceinline__ void mma16816(float* c, const uint32_t* a, const uint32_t* b) {
    asm volatile(
        "mma.sync.aligned.m16n8k16.row.col.f32.bf16.bf16.f32 "
        "{%0,%1,%2,%3}, {%4,%5,%6,%7}, {%8,%9}, {%0,%1,%2,%3};"
        : "+f"(c[0]), "+f"(c[1]), "+f"(c[2]), "+f"(c[3])
        : "r"(a[0]), "r"(a[1]), "r"(a[2]), "r"(a[3]), "r"(b[0]), "r"(b[1]));
}

__device__ __forceinline__ float elu1(float x) {
    return x >= 0.f ? x + 1.f : __expf(x);
}
__device__ __forceinline__ void split2(float v, __nv_bfloat16& hi, __nv_bfloat16& lo) {
    hi = __float2bfloat16_rn(v);
    lo = __float2bfloat16_rn(v - __bfloat162float(hi));
}
__device__ __forceinline__ uint32_t lds32(const __nv_bfloat16* p) {
    return *(const uint32_t*)p;
}

// ============================================================================
// W transpose: g_wt[n][k] = W[k][n]   (W: [512][1536])   [R5-verified]
// ============================================================================
__global__ void transpose_w(const float* __restrict__ W)
{
    __shared__ float t[32][33];
    const int bx = blockIdx.x * 32;   // n base
    const int by = blockIdx.y * 32;   // k base
    const int x = threadIdx.x;
    for (int yy = threadIdx.y; yy < 32; yy += 8)
        t[yy][x] = W[(size_t)(by + yy) * NQKV + bx + x];
    __syncthreads();
    for (int yy = threadIdx.y; yy < 32; yy += 8)
        g_wt[(size_t)(bx + yy) * 512 + by + x] = t[x][yy];
}

// ============================================================================
// Same-index elementwise split: H[i]=hi(src[i]), L[i]=lo(src[i])  [R6-verified]
// ============================================================================
__global__ void conv_split(const float* __restrict__ src,
                           __nv_bfloat16* __restrict__ H,
                           __nv_bfloat16* __restrict__ L)
{
    size_t i4 = (size_t)blockIdx.x * 256 + threadIdx.x;
    float4 v = ((const float4*)src)[i4];
    __nv_bfloat16 h0, h1, h2, h3, l0, l1, l2, l3;
    split2(v.x, h0, l0); split2(v.y, h1, l1); split2(v.z, h2, l2); split2(v.w, h3, l3);
    ((__nv_bfloat162*)H)[i4 * 2]     = __nv_bfloat162(h0, h1);
    ((__nv_bfloat162*)H)[i4 * 2 + 1] = __nv_bfloat162(h2, h3);
    ((__nv_bfloat162*)L)[i4 * 2]     = __nv_bfloat162(l0, l1);
    ((__nv_bfloat162*)L)[i4 * 2 + 1] = __nv_bfloat162(l2, l3);
}

// ============================================================================
// conv_qz: same-index split of q[i]*z   [R6-verified]
// ============================================================================
__global__ void conv_qz()
{
    size_t i4 = (size_t)blockIdx.x * 256 + threadIdx.x;
    size_t e = i4 * 4;
    int row = (int)(e >> 9);          // global row
    int c = (int)(e & 511);           // column; c..c+3 within one 64-wide head
    int b = row >> 13, n = row & 8191;
    float zv = g_z[(size_t)(b * 8 + (c >> 6)) * 8192 + n];
    float4 v = ((const float4*)g_q)[i4];
    v.x *= zv; v.y *= zv; v.z *= zv; v.w *= zv;
    __nv_bfloat16 h0, h1, h2, h3, l0, l1, l2, l3;
    split2(v.x, h0, l0); split2(v.y, h1, l1); split2(v.z, h2, l2); split2(v.w, h3, l3);
    ((__nv_bfloat162*)g_qzh)[i4 * 2]     = __nv_bfloat162(h0, h1);
    ((__nv_bfloat162*)g_qzh)[i4 * 2 + 1] = __nv_bfloat162(h2, h3);
    ((__nv_bfloat162*)g_qzl)[i4 * 2]     = __nv_bfloat162(l0, l1);
    ((__nv_bfloat162*)g_qzl)[i4 * 2 + 1] = __nv_bfloat162(l2, l3);
}

// ============================================================================
// bf16-split GEMM via mma.sync. C tile 128x128, K=512 in 16 chunks of 32.
// Pre-split bf16 sources. Synchronous smem fill (no prefetch regs) +
// __launch_bounds__(256,2) so 2 CTAs/SM overlap load and MMA phases.
// MODE 0: C = X @ W -> split q/k/v, elu+1 on q,k
// MODE 1: C = (q*z) @ Wbig + bias -> Out   (z pre-applied in conv_qz)
// ============================================================================
#define PITCH 40                      // bf16 per smem row (80 B) -> conflict-free frags

template <int MODE>
__global__ __launch_bounds__(256, 2) void gemm_mma(
    const __nv_bfloat16* __restrict__ AH, const __nv_bfloat16* __restrict__ AL,
    const __nv_bfloat16* __restrict__ BHg, const __nv_bfloat16* __restrict__ BLg,
    const float* __restrict__ bias, float* __restrict__ Out)
{
    __shared__ __nv_bfloat16 sAh[128 * PITCH];
    __shared__ __nv_bfloat16 sAl[128 * PITCH];
    __shared__ __nv_bfloat16 sBh[128 * PITCH];
    __shared__ __nv_bfloat16 sBl[128 * PITCH];

    const int tid = threadIdx.x;
    const int wid = tid >> 5, lane = tid & 31;
    const int g = lane >> 2, tig = lane & 3;
    const int m0 = blockIdx.y * 128;
    const int n0 = blockIdx.x * 128;
    const int wm = (wid & 1) * 64;
    const int wn = (wid >> 1) * 32;
    const int bb = m0 >> 13;          // batch (tiles never straddle batches)

    const __nv_bfloat16* BH = BHg + (MODE == 1 ? (size_t)bb * 262144 : 0);
    const __nv_bfloat16* BL = BLg + (MODE == 1 ? (size_t)bb * 262144 : 0);

    // per-thread fill slots: idx = tid + 256*i (i<2); row = idx>>2, ch = idx&3
    const int fr0 = tid >> 2, fch0 = (tid & 3) * 8;
    const int fr1 = (tid + 256) >> 2, fch1 = ((tid + 256) & 3) * 8;

    const __nv_bfloat16* gah0 = AH + (size_t)(m0 + fr0) * 512 + fch0;
    const __nv_bfloat16* gah1 = AH + (size_t)(m0 + fr1) * 512 + fch1;
    const __nv_bfloat16* gal0 = AL + (size_t)(m0 + fr0) * 512 + fch0;
    const __nv_bfloat16* gal1 = AL + (size_t)(m0 + fr1) * 512 + fch1;
    const __nv_bfloat16* gbh0 = BH + (size_t)(n0 + fr0) * 512 + fch0;
    const __nv_bfloat16* gbh1 = BH + (size_t)(n0 + fr1) * 512 + fch1;
    const __nv_bfloat16* gbl0 = BL + (size_t)(n0 + fr0) * 512 + fch0;
    const __nv_bfloat16* gbl1 = BL + (size_t)(n0 + fr1) * 512 + fch1;

    float acc[4][4][4];
#pragma unroll
    for (int i = 0; i < 4; i++)
#pragma unroll
        for (int j = 0; j < 4; j++)
#pragma unroll
            for (int t = 0; t < 4; t++) acc[i][j][t] = 0.f;

    for (int kc = 0; kc < 16; kc++) {
        const int k0 = kc * 32;
        __syncthreads();   // previous compute done before overwriting smem

        // ---- synchronous fill: 8 LDG.128 batched (MLP), then 8 STS ----
        {
            uint4 t0 = *(const uint4*)(gah0 + k0);
            uint4 t1 = *(const uint4*)(gah1 + k0);
            uint4 t2 = *(const uint4*)(gal0 + k0);
            uint4 t3 = *(const uint4*)(gal1 + k0);
            uint4 t4 = *(const uint4*)(gbh0 + k0);
            uint4 t5 = *(const uint4*)(gbh1 + k0);
            uint4 t6 = *(const uint4*)(gbl0 + k0);
            uint4 t7 = *(const uint4*)(gbl1 + k0);
            *(uint4*)(sAh + fr0 * PITCH + fch0) = t0;
            *(uint4*)(sAh + fr1 * PITCH + fch1) = t1;
            *(uint4*)(sAl + fr0 * PITCH + fch0) = t2;
            *(uint4*)(sAl + fr1 * PITCH + fch1) = t3;
            *(uint4*)(sBh + fr0 * PITCH + fch0) = t4;
            *(uint4*)(sBh + fr1 * PITCH + fch1) = t5;
            *(uint4*)(sBl + fr0 * PITCH + fch0) = t6;
            *(uint4*)(sBl + fr1 * PITCH + fch1) = t7;
        }
        __syncthreads();

        // ---- compute: 2 k-halves of 16; A frags upfront, B frags per-nt ----
#pragma unroll
        for (int ks = 0; ks < 2; ks++) {
            const int ko = ks * 16 + tig * 2;
            uint32_t ah[4][4], al[4][4];
#pragma unroll
            for (int mt = 0; mt < 4; mt++) {
                const int r = wm + mt * 16 + g;
                ah[mt][0] = lds32(sAh + r * PITCH + ko);
                ah[mt][1] = lds32(sAh + (r + 8) * PITCH + ko);
                ah[mt][2] = lds32(sAh + r * PITCH + ko + 8);
                ah[mt][3] = lds32(sAh + (r + 8) * PITCH + ko + 8);
                al[mt][0] = lds32(sAl + r * PITCH + ko);
                al[mt][1] = lds32(sAl + (r + 8) * PITCH + ko);
                al[mt][2] = lds32(sAl + r * PITCH + ko + 8);
                al[mt][3] = lds32(sAl + (r + 8) * PITCH + ko + 8);
            }
#pragma unroll
            for (int nt = 0; nt < 4; nt++) {
                const int rn = wn + nt * 8 + g;
                uint32_t bh[2], bl[2];
                bh[0] = lds32(sBh + rn * PITCH + ko);
                bh[1] = lds32(sBh + rn * PITCH + ko + 8);
                bl[0] = lds32(sBl + rn * PITCH + ko);
                bl[1] = lds32(sBl + rn * PITCH + ko + 8);
#pragma unroll
                for (int mt = 0; mt < 4; mt++) {
                    mma16816(acc[mt][nt], ah[mt], bh);
                    mma16816(acc[mt][nt], ah[mt], bl);
                    mma16816(acc[mt][nt], al[mt], bh);
                }
            }
        }
    }

    // -------- epilogue [R5-verified] --------
    if (MODE == 0) {
        float* dst = (n0 < 512) ? g_q : (n0 < 1024 ? g_k : g_v);
        const bool act = (n0 < 1024);
        const int cb = (n0 & 511) + wn;
#pragma unroll
        for (int mt = 0; mt < 4; mt++) {
            int r0 = m0 + wm + mt * 16 + g;
#pragma unroll
            for (int nt = 0; nt < 4; nt++) {
                int c = cb + nt * 8 + tig * 2;
                float v0 = acc[mt][nt][0], v1 = acc[mt][nt][1];
                float v2 = acc[mt][nt][2], v3 = acc[mt][nt][3];
                if (act) { v0 = elu1(v0); v1 = elu1(v1); v2 = elu1(v2); v3 = elu1(v3); }
                *(float2*)&dst[(size_t)r0 * 512 + c]       = make_float2(v0, v1);
                *(float2*)&dst[(size_t)(r0 + 8) * 512 + c] = make_float2(v2, v3);
            }
        }
    } else {
        const int cb = n0 + wn;
#pragma unroll
        for (int mt = 0; mt < 4; mt++) {
            int r0 = m0 + wm + mt * 16 + g;
#pragma unroll
            for (int nt = 0; nt < 4; nt++) {
                int c = cb + nt * 8 + tig * 2;
                float b0 = bias[c], b1 = bias[c + 1];
                *(float2*)&Out[(size_t)r0 * 512 + c] =
                    make_float2(acc[mt][nt][0] + b0, acc[mt][nt][1] + b1);
                *(float2*)&Out[(size_t)(r0 + 8) * 512 + c] =
                    make_float2(acc[mt][nt][2] + b0, acc[mt][nt][3] + b1);
            }
        }
    }
}

// ============================================================================
// kv partial reduce + combine (fp32 SIMT) [R1/R5-verified]
// ============================================================================
__global__ __launch_bounds__(256, 4) void kv_reduce()
{
    __shared__ float ks[8][64];
    __shared__ float vs[8][64];
    const int bh = blockIdx.x;
    const int b = bh >> 3, h = bh & 7;
    const int nbase = blockIdx.y * 512;
    const int tid = threadIdx.x;
    const int tx = tid & 15, ty = tid >> 4;

    float acc[4][4];
#pragma unroll
    for (int i = 0; i < 4; i++)
#pragma unroll
        for (int j = 0; j < 4; j++) acc[i][j] = 0.f;
    float ksacc[4] = {0.f, 0.f, 0.f, 0.f};

    const int lr = (tid & 127) >> 4;
    const int lc = tid & 15;
    const float* src = (tid < 128) ? g_k : g_v;
    float* sdst = (tid < 128) ? &ks[lr][lc * 4] : &vs[lr][lc * 4];

    for (int r0 = 0; r0 < 512; r0 += 8) {
        int n = nbase + r0 + lr;
        float4 val = *(const float4*)&src[((size_t)(b * 8192 + n)) * 512 + h * 64 + lc * 4];
        *(float4*)sdst = val;
        __syncthreads();
#pragma unroll
        for (int r = 0; r < 8; r++) {
            float kf[4], vf[4];
            *(float4*)kf = *(float4*)&ks[r][tx * 4];
            *(float4*)vf = *(float4*)&vs[r][ty * 4];
#pragma unroll
            for (int i = 0; i < 4; i++)
#pragma unroll
                for (int j = 0; j < 4; j++) acc[i][j] += kf[i] * vf[j];
            if (ty == 0) {
#pragma unroll
                for (int i = 0; i < 4; i++) ksacc[i] += kf[i];
            }
        }
        __syncthreads();
    }

    const size_t base = (size_t)(bh * 16 + blockIdx.y) * 4160;
#pragma unroll
    for (int i = 0; i < 4; i++)
#pragma unroll
        for (int j = 0; j < 4; j++)
            g_kvpart[base + (tx * 4 + i) * 64 + ty * 4 + j] = acc[i][j];
    if (ty == 0) {
#pragma unroll
        for (int i = 0; i < 4; i++) g_kvpart[base + 4096 + tx * 4 + i] = ksacc[i];
    }
}

__global__ void kv_combine()
{
    const int bh = blockIdx.x;
    const int i0 = blockIdx.y * 260;
    const int iend = (i0 + 260 < 4160) ? i0 + 260 : 4160;
    for (int i = i0 + threadIdx.x; i < iend; i += 256) {
        float s = 0.f;
#pragma unroll
        for (int c = 0; c < 16; c++) s += g_kvpart[(size_t)(bh * 16 + c) * 4160 + i];
        g_kv[(size_t)bh * 4160 + i] = s;
    }
}

// ============================================================================
// Wbig^T bf16 hi/lo: [b][j][r] = sum_m kv[b,h,d,m] * w_out[h*64+m][j], r=h*64+d
// ============================================================================
__global__ void make_wbig(const float* __restrict__ Wout)
{
    const int r = blockIdx.x;          // h*64+d
    const int b = blockIdx.y;
    const int h = r >> 6, d = r & 63;
    __shared__ float kvrow[64];
    if (threadIdx.x < 64)
        kvrow[threadIdx.x] = g_kv[(size_t)(b * 8 + h) * 4160 + d * 64 + threadIdx.x];
    __syncthreads();
    float acc[4] = {0.f, 0.f, 0.f, 0.f};
    for (int m = 0; m < 64; m++) {
        float kvv = kvrow[m];
        const float* wrow = Wout + (size_t)(h * 64 + m) * 512;
#pragma unroll
        for (int i = 0; i < 4; i++) acc[i] += kvv * wrow[threadIdx.x + i * 128];
    }
#pragma unroll
    for (int i = 0; i < 4; i++) {
        int j = threadIdx.x + i * 128;
        __nv_bfloat16 hi, lo;
        split2(acc[i], hi, lo);
        g_wbth[(size_t)b * 262144 + (size_t)j * 512 + r] = hi;
        g_wbtl[(size_t)b * 262144 + (size_t)j * 512 + r] = lo;
    }
}

// ============================================================================
// z = 1 / (q . ksum + 1e-6)    [R1/R5-verified]
// ============================================================================
__global__ void compute_z()
{
    const int idx = blockIdx.x * 512 + threadIdx.x;
    const int n = idx & 8191;
    const int bh = idx >> 13;
    const int b = bh >> 3, h = bh & 7;
    const float* qrow = g_q + (size_t)(b * 8192 + n) * 512 + h * 64;
    const float* ksum = g_kv + (size_t)bh * 4160 + 4096;
    float s = 0.f;
#pragma unroll
    for (int i = 0; i < 16; i++) {
        float4 qv = *(const float4*)(qrow + i * 4);
        float4 kv = *(const float4*)(ksum + i * 4);
        s += qv.x * kv.x + qv.y * kv.y + qv.z * kv.z + qv.w * kv.w;
    }
    g_z[idx] = 1.0f / (s + 1e-6f);
}

// ============================================================================
extern "C" void kernel_launch(void* const* d_in, const int* in_sizes, int n_in,
                              void* d_out, int out_size)
{
    const float* x     = (const float*)d_in[0];   // [4,8192,512]
    const float* w_qkv = (const float*)d_in[1];   // [512,1536]
    const float* w_out = (const float*)d_in[2];   // [512,512]
    const float* b_out = (const float*)d_in[3];   // [512]
    float* out = (float*)d_out;                   // [4,8192,512]

    float* wt_p;    cudaGetSymbolAddress((void**)&wt_p,  g_wt);
    __nv_bfloat16 *xh_p, *xl_p, *wth_p, *wtl_p, *qzh_p, *qzl_p, *wbth_p, *wbtl_p;
    cudaGetSymbolAddress((void**)&xh_p,  g_xh);
    cudaGetSymbolAddress((void**)&xl_p,  g_xl);
    cudaGetSymbolAddress((void**)&wth_p, g_wth);
    cudaGetSymbolAddress((void**)&wtl_p, g_wtl);
    cudaGetSymbolAddress((void**)&qzh_p, g_qzh);
    cudaGetSymbolAddress((void**)&qzl_p, g_qzl);
    cudaGetSymbolAddress((void**)&wbth_p, g_wbth);
    cudaGetSymbolAddress((void**)&wbtl_p, g_wbtl);

    transpose_w<<<dim3(48, 16), dim3(32, 8)>>>(w_qkv);
    conv_split<<<16384, 256>>>(x, xh_p, xl_p);                 // X: 16.7M elems
    conv_split<<<768, 256>>>(wt_p, wth_p, wtl_p);              // W^T: 0.79M elems
    gemm_mma<0><<<dim3(12, 256), 256>>>(xh_p, xl_p, wth_p, wtl_p, nullptr, nullptr);
    kv_reduce<<<dim3(32, 16), 256>>>();
    kv_combine<<<dim3(32, 16), 256>>>();
    make_wbig<<<dim3(512, 4), 128>>>(w_out);
    compute_z<<<512, 512>>>();
    conv_qz<<<16384, 256>>>();
    gemm_mma<1><<<dim3(4, 256), 256>>>(qzh_p, qzl_p, wbth_p, wbtl_p, b_out, out);
}

// round 8
// speedup vs baseline: 1.1586x; 1.0795x over previous
#include <cuda_runtime.h>
#include <cuda_bf16.h>
#include <math.h>
#include <stdint.h>

#define MROWS (4 * 8192)          // 32768 rows total
#define DIMK  512
#define NQKV  1536

// ---------------- scratch (device globals; no allocation allowed) ----------
__device__ float g_q[MROWS * 512];          // elu(q)+1 fp32
__device__ float g_k[MROWS * 512];          // elu(k)+1 fp32
__device__ float g_v[MROWS * 512];          // v fp32
__device__ float g_kvpart[32 * 16 * 4160];  // per (bh,chunk): 64x64 kv + 64 ksum
__device__ float g_kv[32 * 4160];
__device__ float g_wt[NQKV * 512];          // w_qkv^T fp32 [n][k]

__device__ __nv_bfloat16 g_xh[MROWS * 512];   // x hi/lo (same index as x)
__device__ __nv_bfloat16 g_xl[MROWS * 512];
__device__ __nv_bfloat16 g_wth[NQKV * 512];   // w^T hi/lo (same index as g_wt)
__device__ __nv_bfloat16 g_wtl[NQKV * 512];
__device__ __nv_bfloat16 g_qzh[MROWS * 512];  // (q*z) hi/lo (same index as g_q)
__device__ __nv_bfloat16 g_qzl[MROWS * 512];
__device__ __nv_bfloat16 g_wbth[4 * 512 * 512]; // Wbig^T hi/lo [b][j][r]
__device__ __nv_bfloat16 g_wbtl[4 * 512 * 512];

// ---------------- helpers ---------------------------------------------------
__device__ __forceinline__ void mma16816(float* c, const uint32_t* a, const uint32_t* b) {
    asm volatile(
        "mma.sync.aligned.m16n8k16.row.col.f32.bf16.bf16.f32 "
        "{%0,%1,%2,%3}, {%4,%5,%6,%7}, {%8,%9}, {%0,%1,%2,%3};"
        : "+f"(c[0]), "+f"(c[1]), "+f"(c[2]), "+f"(c[3])
        : "r"(a[0]), "r"(a[1]), "r"(a[2]), "r"(a[3]), "r"(b[0]), "r"(b[1]));
}
__device__ __forceinline__ void ldsm4(uint32_t* r, uint32_t a) {
    asm volatile("ldmatrix.sync.aligned.m8n8.x4.shared.b16 {%0,%1,%2,%3}, [%4];"
        : "=r"(r[0]), "=r"(r[1]), "=r"(r[2]), "=r"(r[3]) : "r"(a));
}
__device__ __forceinline__ uint32_t smem_u32(const void* p) {
    uint32_t a;
    asm("{ .reg .u64 t; cvta.to.shared.u64 t, %1; cvt.u32.u64 %0, t; }" : "=r"(a) : "l"(p));
    return a;
}
__device__ __forceinline__ float elu1(float x) {
    return x >= 0.f ? x + 1.f : __expf(x);
}
__device__ __forceinline__ void split2(float v, __nv_bfloat16& hi, __nv_bfloat16& lo) {
    hi = __float2bfloat16_rn(v);
    lo = __float2bfloat16_rn(v - __bfloat162float(hi));
}

// ============================================================================
// W transpose: g_wt[n][k] = W[k][n]   (W: [512][1536])   [R5-verified]
// ============================================================================
__global__ void transpose_w(const float* __restrict__ W)
{
    __shared__ float t[32][33];
    const int bx = blockIdx.x * 32;   // n base
    const int by = blockIdx.y * 32;   // k base
    const int x = threadIdx.x;
    for (int yy = threadIdx.y; yy < 32; yy += 8)
        t[yy][x] = W[(size_t)(by + yy) * NQKV + bx + x];
    __syncthreads();
    for (int yy = threadIdx.y; yy < 32; yy += 8)
        g_wt[(size_t)(bx + yy) * 512 + by + x] = t[x][yy];
}

// ============================================================================
// Same-index elementwise split: H[i]=hi(src[i]), L[i]=lo(src[i])  [R6-verified]
// ============================================================================
__global__ void conv_split(const float* __restrict__ src,
                           __nv_bfloat16* __restrict__ H,
                           __nv_bfloat16* __restrict__ L)
{
    size_t i4 = (size_t)blockIdx.x * 256 + threadIdx.x;
    float4 v = ((const float4*)src)[i4];
    __nv_bfloat16 h0, h1, h2, h3, l0, l1, l2, l3;
    split2(v.x, h0, l0); split2(v.y, h1, l1); split2(v.z, h2, l2); split2(v.w, h3, l3);
    ((__nv_bfloat162*)H)[i4 * 2]     = __nv_bfloat162(h0, h1);
    ((__nv_bfloat162*)H)[i4 * 2 + 1] = __nv_bfloat162(h2, h3);
    ((__nv_bfloat162*)L)[i4 * 2]     = __nv_bfloat162(l0, l1);
    ((__nv_bfloat162*)L)[i4 * 2 + 1] = __nv_bfloat162(l2, l3);
}

// ============================================================================
// z_split: fused compute_z + conv_qz. One block per row (128 threads).
// part-dot via shfl within the 16-thread head group; z broadcast; scale+split.
// ============================================================================
__global__ __launch_bounds__(128) void z_split()
{
    const int row = blockIdx.x;            // 0..32767
    const int b = row >> 13;
    const int t = threadIdx.x;             // 0..127
    const int h = t >> 4;                  // head of this thread's 4 elems
    const int e = t * 4;                   // element base within row
    const int d = e & 63;

    float4 q = *(const float4*)(g_q + (size_t)row * 512 + e);
    const float* ks = g_kv + (size_t)(b * 8 + h) * 4160 + 4096 + d;
    float part = q.x * ks[0] + q.y * ks[1] + q.z * ks[2] + q.w * ks[3];
#pragma unroll
    for (int off = 8; off; off >>= 1)
        part += __shfl_xor_sync(0xFFFFFFFFu, part, off);
    const float z = 1.0f / (part + 1e-6f);

    __nv_bfloat16 h0, h1, h2, h3, l0, l1, l2, l3;
    split2(q.x * z, h0, l0); split2(q.y * z, h1, l1);
    split2(q.z * z, h2, l2); split2(q.w * z, h3, l3);
    size_t o2 = ((size_t)row * 512 + e) >> 1;
    ((__nv_bfloat162*)g_qzh)[o2]     = __nv_bfloat162(h0, h1);
    ((__nv_bfloat162*)g_qzh)[o2 + 1] = __nv_bfloat162(h2, h3);
    ((__nv_bfloat162*)g_qzl)[o2]     = __nv_bfloat162(l0, l1);
    ((__nv_bfloat162*)g_qzl)[o2 + 1] = __nv_bfloat162(l2, l3);
}

// ============================================================================
// bf16-split GEMM via mma.sync + ldmatrix. C tile 128x128, K=512, 16 chunks of
// 32. Pre-split bf16 sources; synchronous smem fill; 2 CTAs/SM.
// MODE 0: C = X @ W -> split q/k/v, elu+1 on q,k
// MODE 1: C = (q*z) @ Wbig + bias -> Out
// ============================================================================
#define PITCH 40                      // bf16 per smem row (80 B) -> conflict-free

template <int MODE>
__global__ __launch_bounds__(256, 2) void gemm_mma(
    const __nv_bfloat16* __restrict__ AH, const __nv_bfloat16* __restrict__ AL,
    const __nv_bfloat16* __restrict__ BHg, const __nv_bfloat16* __restrict__ BLg,
    const float* __restrict__ bias, float* __restrict__ Out)
{
    __shared__ __nv_bfloat16 sAh[128 * PITCH];
    __shared__ __nv_bfloat16 sAl[128 * PITCH];
    __shared__ __nv_bfloat16 sBh[128 * PITCH];
    __shared__ __nv_bfloat16 sBl[128 * PITCH];

    const int tid = threadIdx.x;
    const int wid = tid >> 5, lane = tid & 31;
    const int g = lane >> 2, tig = lane & 3;
    const int m0 = blockIdx.y * 128;
    const int n0 = blockIdx.x * 128;
    const int wm = (wid & 1) * 64;
    const int wn = (wid >> 1) * 32;
    const int bb = m0 >> 13;          // batch (tiles never straddle batches)

    const __nv_bfloat16* BH = BHg + (MODE == 1 ? (size_t)bb * 262144 : 0);
    const __nv_bfloat16* BL = BLg + (MODE == 1 ? (size_t)bb * 262144 : 0);

    // per-thread fill slots: idx = tid + 256*i (i<2); row = idx>>2, ch = idx&3
    const int fr0 = tid >> 2, fch0 = (tid & 3) * 8;
    const int fr1 = (tid + 256) >> 2, fch1 = ((tid + 256) & 3) * 8;

    const __nv_bfloat16* gah0 = AH + (size_t)(m0 + fr0) * 512 + fch0;
    const __nv_bfloat16* gah1 = AH + (size_t)(m0 + fr1) * 512 + fch1;
    const __nv_bfloat16* gal0 = AL + (size_t)(m0 + fr0) * 512 + fch0;
    const __nv_bfloat16* gal1 = AL + (size_t)(m0 + fr1) * 512 + fch1;
    const __nv_bfloat16* gbh0 = BH + (size_t)(n0 + fr0) * 512 + fch0;
    const __nv_bfloat16* gbh1 = BH + (size_t)(n0 + fr1) * 512 + fch1;
    const __nv_bfloat16* gbl0 = BL + (size_t)(n0 + fr0) * 512 + fch0;
    const __nv_bfloat16* gbl1 = BL + (size_t)(n0 + fr1) * 512 + fch1;

    // ldmatrix per-lane base addresses (byte offsets into smem arrays):
    // A x4: lanes 0-15 -> rows (wm + lane&15), k-col 0; lanes 16-31 -> same rows, k+8
    const uint32_t aoff =
        (uint32_t)(((wm + (lane & 15)) * PITCH + (lane >> 4) * 8) * 2);
    // B x4 (two nt tiles): rows wn + ((lane>>4)&1)*8 + (lane&7); col ((lane>>3)&1)*8
    const uint32_t boff =
        (uint32_t)(((wn + ((lane >> 4) & 1) * 8 + (lane & 7)) * PITCH +
                    ((lane >> 3) & 1) * 8) * 2);
    const uint32_t aBaseH = smem_u32(sAh) + aoff;
    const uint32_t aBaseL = smem_u32(sAl) + aoff;
    const uint32_t bBaseH = smem_u32(sBh) + boff;
    const uint32_t bBaseL = smem_u32(sBl) + boff;

    float acc[4][4][4];
#pragma unroll
    for (int i = 0; i < 4; i++)
#pragma unroll
        for (int j = 0; j < 4; j++)
#pragma unroll
            for (int t = 0; t < 4; t++) acc[i][j][t] = 0.f;

    for (int kc = 0; kc < 16; kc++) {
        const int k0 = kc * 32;
        __syncthreads();   // previous compute done before overwriting smem

        // ---- synchronous fill: 8 LDG.128 batched (MLP), then 8 STS ----
        {
            uint4 t0 = *(const uint4*)(gah0 + k0);
            uint4 t1 = *(const uint4*)(gah1 + k0);
            uint4 t2 = *(const uint4*)(gal0 + k0);
            uint4 t3 = *(const uint4*)(gal1 + k0);
            uint4 t4 = *(const uint4*)(gbh0 + k0);
            uint4 t5 = *(const uint4*)(gbh1 + k0);
            uint4 t6 = *(const uint4*)(gbl0 + k0);
            uint4 t7 = *(const uint4*)(gbl1 + k0);
            *(uint4*)(sAh + fr0 * PITCH + fch0) = t0;
            *(uint4*)(sAh + fr1 * PITCH + fch1) = t1;
            *(uint4*)(sAl + fr0 * PITCH + fch0) = t2;
            *(uint4*)(sAl + fr1 * PITCH + fch1) = t3;
            *(uint4*)(sBh + fr0 * PITCH + fch0) = t4;
            *(uint4*)(sBh + fr1 * PITCH + fch1) = t5;
            *(uint4*)(sBl + fr0 * PITCH + fch0) = t6;
            *(uint4*)(sBl + fr1 * PITCH + fch1) = t7;
        }
        __syncthreads();

        // ---- compute: 2 k-halves of 16; ldmatrix fragments ----
#pragma unroll
        for (int ks = 0; ks < 2; ks++) {
            const uint32_t kb = (uint32_t)(ks * 32);   // 16 bf16 = 32 bytes
            uint32_t ah[4][4], al[4][4];
#pragma unroll
            for (int mt = 0; mt < 4; mt++) {
                const uint32_t ro = (uint32_t)(mt * 16 * PITCH * 2) + kb;
                ldsm4(ah[mt], aBaseH + ro);
                ldsm4(al[mt], aBaseL + ro);
            }
#pragma unroll
            for (int ntp = 0; ntp < 2; ntp++) {
                const uint32_t ro = (uint32_t)(ntp * 16 * PITCH * 2) + kb;
                uint32_t bh4[4], bl4[4];
                ldsm4(bh4, bBaseH + ro);
                ldsm4(bl4, bBaseL + ro);
#pragma unroll
                for (int half = 0; half < 2; half++) {
                    const int nt = ntp * 2 + half;
                    const uint32_t* bh = bh4 + half * 2;
                    const uint32_t* bl = bl4 + half * 2;
#pragma unroll
                    for (int mt = 0; mt < 4; mt++) {
                        mma16816(acc[mt][nt], ah[mt], bh);
                        mma16816(acc[mt][nt], ah[mt], bl);
                        mma16816(acc[mt][nt], al[mt], bh);
                    }
                }
            }
        }
    }

    // -------- epilogue [R5-verified] --------
    if (MODE == 0) {
        float* dst = (n0 < 512) ? g_q : (n0 < 1024 ? g_k : g_v);
        const bool act = (n0 < 1024);
        const int cb = (n0 & 511) + wn;
#pragma unroll
        for (int mt = 0; mt < 4; mt++) {
            int r0 = m0 + wm + mt * 16 + g;
#pragma unroll
            for (int nt = 0; nt < 4; nt++) {
                int c = cb + nt * 8 + tig * 2;
                float v0 = acc[mt][nt][0], v1 = acc[mt][nt][1];
                float v2 = acc[mt][nt][2], v3 = acc[mt][nt][3];
                if (act) { v0 = elu1(v0); v1 = elu1(v1); v2 = elu1(v2); v3 = elu1(v3); }
                *(float2*)&dst[(size_t)r0 * 512 + c]       = make_float2(v0, v1);
                *(float2*)&dst[(size_t)(r0 + 8) * 512 + c] = make_float2(v2, v3);
            }
        }
    } else {
        const int cb = n0 + wn;
#pragma unroll
        for (int mt = 0; mt < 4; mt++) {
            int r0 = m0 + wm + mt * 16 + g;
#pragma unroll
            for (int nt = 0; nt < 4; nt++) {
                int c = cb + nt * 8 + tig * 2;
                float b0 = bias[c], b1 = bias[c + 1];
                *(float2*)&Out[(size_t)r0 * 512 + c] =
                    make_float2(acc[mt][nt][0] + b0, acc[mt][nt][1] + b1);
                *(float2*)&Out[(size_t)(r0 + 8) * 512 + c] =
                    make_float2(acc[mt][nt][2] + b0, acc[mt][nt][3] + b1);
            }
        }
    }
}

// ============================================================================
// kv partial reduce + combine (fp32 SIMT) [R1/R5-verified]
// ============================================================================
__global__ __launch_bounds__(256, 4) void kv_reduce()
{
    __shared__ float ks[8][64];
    __shared__ float vs[8][64];
    const int bh = blockIdx.x;
    const int b = bh >> 3, h = bh & 7;
    const int nbase = blockIdx.y * 512;
    const int tid = threadIdx.x;
    const int tx = tid & 15, ty = tid >> 4;

    float acc[4][4];
#pragma unroll
    for (int i = 0; i < 4; i++)
#pragma unroll
        for (int j = 0; j < 4; j++) acc[i][j] = 0.f;
    float ksacc[4] = {0.f, 0.f, 0.f, 0.f};

    const int lr = (tid & 127) >> 4;
    const int lc = tid & 15;
    const float* src = (tid < 128) ? g_k : g_v;
    float* sdst = (tid < 128) ? &ks[lr][lc * 4] : &vs[lr][lc * 4];

    for (int r0 = 0; r0 < 512; r0 += 8) {
        int n = nbase + r0 + lr;
        float4 val = *(const float4*)&src[((size_t)(b * 8192 + n)) * 512 + h * 64 + lc * 4];
        *(float4*)sdst = val;
        __syncthreads();
#pragma unroll
        for (int r = 0; r < 8; r++) {
            float kf[4], vf[4];
            *(float4*)kf = *(float4*)&ks[r][tx * 4];
            *(float4*)vf = *(float4*)&vs[r][ty * 4];
#pragma unroll
            for (int i = 0; i < 4; i++)
#pragma unroll
                for (int j = 0; j < 4; j++) acc[i][j] += kf[i] * vf[j];
            if (ty == 0) {
#pragma unroll
                for (int i = 0; i < 4; i++) ksacc[i] += kf[i];
            }
        }
        __syncthreads();
    }

    const size_t base = (size_t)(bh * 16 + blockIdx.y) * 4160;
#pragma unroll
    for (int i = 0; i < 4; i++)
#pragma unroll
        for (int j = 0; j < 4; j++)
            g_kvpart[base + (tx * 4 + i) * 64 + ty * 4 + j] = acc[i][j];
    if (ty == 0) {
#pragma unroll
        for (int i = 0; i < 4; i++) g_kvpart[base + 4096 + tx * 4 + i] = ksacc[i];
    }
}

__global__ void kv_combine()
{
    const int bh = blockIdx.x;
    const int i0 = blockIdx.y * 260;
    const int iend = (i0 + 260 < 4160) ? i0 + 260 : 4160;
    for (int i = i0 + threadIdx.x; i < iend; i += 256) {
        float s = 0.f;
#pragma unroll
        for (int c = 0; c < 16; c++) s += g_kvpart[(size_t)(bh * 16 + c) * 4160 + i];
        g_kv[(size_t)bh * 4160 + i] = s;
    }
}

// ============================================================================
// Wbig^T bf16 hi/lo: [b][j][r] = sum_m kv[b,h,d,m] * w_out[h*64+m][j], r=h*64+d
// ============================================================================
__global__ void make_wbig(const float* __restrict__ Wout)
{
    const int r = blockIdx.x;          // h*64+d
    const int b = blockIdx.y;
    const int h = r >> 6, d = r & 63;
    __shared__ float kvrow[64];
    if (threadIdx.x < 64)
        kvrow[threadIdx.x] = g_kv[(size_t)(b * 8 + h) * 4160 + d * 64 + threadIdx.x];
    __syncthreads();
    float acc[4] = {0.f, 0.f, 0.f, 0.f};
    for (int m = 0; m < 64; m++) {
        float kvv = kvrow[m];
        const float* wrow = Wout + (size_t)(h * 64 + m) * 512;
#pragma unroll
        for (int i = 0; i < 4; i++) acc[i] += kvv * wrow[threadIdx.x + i * 128];
    }
#pragma unroll
    for (int i = 0; i < 4; i++) {
        int j = threadIdx.x + i * 128;
        __nv_bfloat16 hi, lo;
        split2(acc[i], hi, lo);
        g_wbth[(size_t)b * 262144 + (size_t)j * 512 + r] = hi;
        g_wbtl[(size_t)b * 262144 + (size_t)j * 512 + r] = lo;
    }
}

// ============================================================================
extern "C" void kernel_launch(void* const* d_in, const int* in_sizes, int n_in,
                              void* d_out, int out_size)
{
    const float* x     = (const float*)d_in[0];   // [4,8192,512]
    const float* w_qkv = (const float*)d_in[1];   // [512,1536]
    const float* w_out = (const float*)d_in[2];   // [512,512]
    const float* b_out = (const float*)d_in[3];   // [512]
    float* out = (float*)d_out;                   // [4,8192,512]

    float* wt_p;    cudaGetSymbolAddress((void**)&wt_p,  g_wt);
    __nv_bfloat16 *xh_p, *xl_p, *wth_p, *wtl_p, *qzh_p, *qzl_p, *wbth_p, *wbtl_p;
    cudaGetSymbolAddress((void**)&xh_p,  g_xh);
    cudaGetSymbolAddress((void**)&xl_p,  g_xl);
    cudaGetSymbolAddress((void**)&wth_p, g_wth);
    cudaGetSymbolAddress((void**)&wtl_p, g_wtl);
    cudaGetSymbolAddress((void**)&qzh_p, g_qzh);
    cudaGetSymbolAddress((void**)&qzl_p, g_qzl);
    cudaGetSymbolAddress((void**)&wbth_p, g_wbth);
    cudaGetSymbolAddress((void**)&wbtl_p, g_wbtl);

    transpose_w<<<dim3(48, 16), dim3(32, 8)>>>(w_qkv);
    conv_split<<<16384, 256>>>(x, xh_p, xl_p);                 // X
    conv_split<<<768, 256>>>(wt_p, wth_p, wtl_p);              // W^T
    gemm_mma<0><<<dim3(12, 256), 256>>>(xh_p, xl_p, wth_p, wtl_p, nullptr, nullptr);
    kv_reduce<<<dim3(32, 16), 256>>>();
    kv_combine<<<dim3(32, 16), 256>>>();
    make_wbig<<<dim3(512, 4), 128>>>(w_out);
    z_split<<<32768, 128>>>();
    gemm_mma<1><<<dim3(4, 256), 256>>>(qzh_p, qzl_p, wbth_p, wbtl_p, b_out, out);
}

// round 9
// speedup vs baseline: 1.2577x; 1.0855x over previous
#include <cuda_runtime.h>
#include <cuda_bf16.h>
#include <math.h>
#include <stdint.h>

#define MROWS (4 * 8192)          // 32768 rows total
#define DIMK  512
#define NQKV  1536

// ---------------- scratch (device globals; no allocation allowed) ----------
__device__ float g_q[MROWS * 512];          // elu(q)+1 fp32
__device__ float g_k[MROWS * 512];          // elu(k)+1 fp32
__device__ float g_v[MROWS * 512];          // v fp32
__device__ float g_kvpart[32 * 16 * 4160];  // per (bh,chunk): 64x64 kv + 64 ksum
__device__ float g_kv[32 * 4160];
__device__ float g_wt[NQKV * 512];          // w_qkv^T fp32 [n][k]

__device__ __nv_bfloat16 g_xh[MROWS * 512];   // x hi/lo (same index as x)
__device__ __nv_bfloat16 g_xl[MROWS * 512];
__device__ __nv_bfloat16 g_wth[NQKV * 512];   // w^T hi/lo (same index as g_wt)
__device__ __nv_bfloat16 g_wtl[NQKV * 512];
__device__ __nv_bfloat16 g_qzh[MROWS * 512];  // (q*z) hi/lo (same index as g_q)
__device__ __nv_bfloat16 g_qzl[MROWS * 512];
__device__ __nv_bfloat16 g_wbth[4 * 512 * 512]; // Wbig^T hi/lo [b][j][r]
__device__ __nv_bfloat16 g_wbtl[4 * 512 * 512];

// ---------------- helpers ---------------------------------------------------
__device__ __forceinline__ void mma16816(float* c, const uint32_t* a, const uint32_t* b) {
    asm volatile(
        "mma.sync.aligned.m16n8k16.row.col.f32.bf16.bf16.f32 "
        "{%0,%1,%2,%3}, {%4,%5,%6,%7}, {%8,%9}, {%0,%1,%2,%3};"
        : "+f"(c[0]), "+f"(c[1]), "+f"(c[2]), "+f"(c[3])
        : "r"(a[0]), "r"(a[1]), "r"(a[2]), "r"(a[3]), "r"(b[0]), "r"(b[1]));
}
__device__ __forceinline__ void ldsm4(uint32_t* r, uint32_t a) {
    asm volatile("ldmatrix.sync.aligned.m8n8.x4.shared.b16 {%0,%1,%2,%3}, [%4];"
        : "=r"(r[0]), "=r"(r[1]), "=r"(r[2]), "=r"(r[3]) : "r"(a));
}
__device__ __forceinline__ uint32_t smem_u32(const void* p) {
    uint32_t a;
    asm("{ .reg .u64 t; cvta.to.shared.u64 t, %1; cvt.u32.u64 %0, t; }" : "=r"(a) : "l"(p));
    return a;
}
__device__ __forceinline__ void cp16(uint32_t s, const void* g) {
    asm volatile("cp.async.cg.shared.global [%0], [%1], 16;" :: "r"(s), "l"(g));
}
__device__ __forceinline__ float elu1(float x) {
    return x >= 0.f ? x + 1.f : __expf(x);
}
__device__ __forceinline__ void split2(float v, __nv_bfloat16& hi, __nv_bfloat16& lo) {
    hi = __float2bfloat16_rn(v);
    lo = __float2bfloat16_rn(v - __bfloat162float(hi));
}

// ============================================================================
// W transpose: g_wt[n][k] = W[k][n]   (W: [512][1536])   [R5-verified]
// ============================================================================
__global__ void transpose_w(const float* __restrict__ W)
{
    __shared__ float t[32][33];
    const int bx = blockIdx.x * 32;   // n base
    const int by = blockIdx.y * 32;   // k base
    const int x = threadIdx.x;
    for (int yy = threadIdx.y; yy < 32; yy += 8)
        t[yy][x] = W[(size_t)(by + yy) * NQKV + bx + x];
    __syncthreads();
    for (int yy = threadIdx.y; yy < 32; yy += 8)
        g_wt[(size_t)(bx + yy) * 512 + by + x] = t[x][yy];
}

// ============================================================================
// Same-index elementwise split  [R6-verified]
// ============================================================================
__global__ void conv_split(const float* __restrict__ src,
                           __nv_bfloat16* __restrict__ H,
                           __nv_bfloat16* __restrict__ L)
{
    size_t i4 = (size_t)blockIdx.x * 256 + threadIdx.x;
    float4 v = ((const float4*)src)[i4];
    __nv_bfloat16 h0, h1, h2, h3, l0, l1, l2, l3;
    split2(v.x, h0, l0); split2(v.y, h1, l1); split2(v.z, h2, l2); split2(v.w, h3, l3);
    ((__nv_bfloat162*)H)[i4 * 2]     = __nv_bfloat162(h0, h1);
    ((__nv_bfloat162*)H)[i4 * 2 + 1] = __nv_bfloat162(h2, h3);
    ((__nv_bfloat162*)L)[i4 * 2]     = __nv_bfloat162(l0, l1);
    ((__nv_bfloat162*)L)[i4 * 2 + 1] = __nv_bfloat162(l2, l3);
}

// ============================================================================
// z_split: fused compute_z + conv_qz  [R8-verified]
// ============================================================================
__global__ __launch_bounds__(128) void z_split()
{
    const int row = blockIdx.x;            // 0..32767
    const int b = row >> 13;
    const int t = threadIdx.x;             // 0..127
    const int h = t >> 4;
    const int e = t * 4;
    const int d = e & 63;

    float4 q = *(const float4*)(g_q + (size_t)row * 512 + e);
    const float* ks = g_kv + (size_t)(b * 8 + h) * 4160 + 4096 + d;
    float part = q.x * ks[0] + q.y * ks[1] + q.z * ks[2] + q.w * ks[3];
#pragma unroll
    for (int off = 8; off; off >>= 1)
        part += __shfl_xor_sync(0xFFFFFFFFu, part, off);
    const float z = 1.0f / (part + 1e-6f);

    __nv_bfloat16 h0, h1, h2, h3, l0, l1, l2, l3;
    split2(q.x * z, h0, l0); split2(q.y * z, h1, l1);
    split2(q.z * z, h2, l2); split2(q.w * z, h3, l3);
    size_t o2 = ((size_t)row * 512 + e) >> 1;
    ((__nv_bfloat162*)g_qzh)[o2]     = __nv_bfloat162(h0, h1);
    ((__nv_bfloat162*)g_qzh)[o2 + 1] = __nv_bfloat162(h2, h3);
    ((__nv_bfloat162*)g_qzl)[o2]     = __nv_bfloat162(l0, l1);
    ((__nv_bfloat162*)g_qzl)[o2 + 1] = __nv_bfloat162(l2, l3);
}

// ============================================================================
// bf16-split GEMM: mma.sync + ldmatrix + cp.async double buffering.
// C tile 128x128, K=512 in 32 chunks of 16. Static smem = 48KB exactly:
// 8 arrays (Ah,Al,Bh,Bl x 2 buffers) of 128 rows x PITCH(24) bf16 = 6144B.
// One __syncthreads per chunk; next chunk's cp.async issued after the sync.
// MODE 0: C = X @ W -> split q/k/v, elu+1 on q,k
// MODE 1: C = (q*z) @ Wbig + bias -> Out
// ============================================================================
#define PITCH 24                      // bf16/row (48 B) -> ldmatrix conflict-free
#define ASZ   (128 * PITCH)           // elems per array (6144 B)

template <int MODE>
__global__ __launch_bounds__(256, 2) void gemm_mma(
    const __nv_bfloat16* __restrict__ AH, const __nv_bfloat16* __restrict__ AL,
    const __nv_bfloat16* __restrict__ BHg, const __nv_bfloat16* __restrict__ BLg,
    const float* __restrict__ bias, float* __restrict__ Out)
{
    __shared__ __nv_bfloat16 smem[8 * ASZ];   // [buf][Ah,Al,Bh,Bl]

    const int tid = threadIdx.x;
    const int wid = tid >> 5, lane = tid & 31;
    const int g = lane >> 2, tig = lane & 3;
    const int m0 = blockIdx.y * 128;
    const int n0 = blockIdx.x * 128;
    const int wm = (wid & 1) * 64;
    const int wn = (wid >> 1) * 32;
    const int bb = m0 >> 13;          // batch (tiles never straddle batches)

    const __nv_bfloat16* BH = BHg + (MODE == 1 ? (size_t)bb * 262144 : 0);
    const __nv_bfloat16* BL = BLg + (MODE == 1 ? (size_t)bb * 262144 : 0);

    // fill mapping: thread t -> row = t>>1, k-slot = (t&1)*8 (one cp16 per array)
    const int frow = tid >> 1, fk = (tid & 1) * 8;
    const uint32_t sOff = (uint32_t)((frow * PITCH + fk) * 2);
    const __nv_bfloat16* gah = AH + (size_t)(m0 + frow) * 512 + fk;
    const __nv_bfloat16* gal = AL + (size_t)(m0 + frow) * 512 + fk;
    const __nv_bfloat16* gbh = BH + (size_t)(n0 + frow) * 512 + fk;
    const __nv_bfloat16* gbl = BL + (size_t)(n0 + frow) * 512 + fk;

    const uint32_t sBase = smem_u32(smem);

    // ldmatrix per-lane offsets (bytes)
    const uint32_t aoff =
        (uint32_t)(((wm + (lane & 15)) * PITCH + (lane >> 4) * 8) * 2);
    const uint32_t boff =
        (uint32_t)(((wn + ((lane >> 4) & 1) * 8 + (lane & 7)) * PITCH +
                    ((lane >> 3) & 1) * 8) * 2);

    float acc[4][4][4];
#pragma unroll
    for (int i = 0; i < 4; i++)
#pragma unroll
        for (int j = 0; j < 4; j++)
#pragma unroll
            for (int t = 0; t < 4; t++) acc[i][j][t] = 0.f;

    // ---- prefetch chunk 0 into buffer 0 ----
    {
        const uint32_t b0 = sBase;
        cp16(b0 + 0 * ASZ * 2 + sOff, gah);
        cp16(b0 + 1 * ASZ * 2 + sOff, gal);
        cp16(b0 + 2 * ASZ * 2 + sOff, gbh);
        cp16(b0 + 3 * ASZ * 2 + sOff, gbl);
        asm volatile("cp.async.commit_group;" ::: "memory");
    }

    for (int kc = 0; kc < 32; kc++) {
        const int buf = kc & 1;
        asm volatile("cp.async.wait_group 0;" ::: "memory");  // chunk kc landed
        __syncthreads();   // data visible; all warps done with buf^1 reads

        // ---- issue chunk kc+1 into the other buffer (overlaps compute) ----
        if (kc < 31) {
            const int k0 = (kc + 1) * 16;
            const uint32_t nb = sBase + (uint32_t)((buf ^ 1) * 4 * ASZ * 2);
            cp16(nb + 0 * ASZ * 2 + sOff, gah + k0);
            cp16(nb + 1 * ASZ * 2 + sOff, gal + k0);
            cp16(nb + 2 * ASZ * 2 + sOff, gbh + k0);
            cp16(nb + 3 * ASZ * 2 + sOff, gbl + k0);
            asm volatile("cp.async.commit_group;" ::: "memory");
        }

        // ---- compute on buf: one k16, ldmatrix fragments [R8-verified] ----
        const uint32_t cb = sBase + (uint32_t)(buf * 4 * ASZ * 2);
        const uint32_t aBaseH = cb + aoff;
        const uint32_t aBaseL = cb + ASZ * 2 + aoff;
        const uint32_t bBaseH = cb + 2 * ASZ * 2 + boff;
        const uint32_t bBaseL = cb + 3 * ASZ * 2 + boff;

        uint32_t ah[4][4], al[4][4];
#pragma unroll
        for (int mt = 0; mt < 4; mt++) {
            const uint32_t ro = (uint32_t)(mt * 16 * PITCH * 2);
            ldsm4(ah[mt], aBaseH + ro);
            ldsm4(al[mt], aBaseL + ro);
        }
#pragma unroll
        for (int ntp = 0; ntp < 2; ntp++) {
            const uint32_t ro = (uint32_t)(ntp * 16 * PITCH * 2);
            uint32_t bh4[4], bl4[4];
            ldsm4(bh4, bBaseH + ro);
            ldsm4(bl4, bBaseL + ro);
#pragma unroll
            for (int half = 0; half < 2; half++) {
                const int nt = ntp * 2 + half;
                const uint32_t* bh = bh4 + half * 2;
                const uint32_t* bl = bl4 + half * 2;
#pragma unroll
                for (int mt = 0; mt < 4; mt++) {
                    mma16816(acc[mt][nt], ah[mt], bh);
                    mma16816(acc[mt][nt], ah[mt], bl);
                    mma16816(acc[mt][nt], al[mt], bh);
                }
            }
        }
    }

    // -------- epilogue [R5-verified] --------
    if (MODE == 0) {
        float* dst = (n0 < 512) ? g_q : (n0 < 1024 ? g_k : g_v);
        const bool act = (n0 < 1024);
        const int cb2 = (n0 & 511) + wn;
#pragma unroll
        for (int mt = 0; mt < 4; mt++) {
            int r0 = m0 + wm + mt * 16 + g;
#pragma unroll
            for (int nt = 0; nt < 4; nt++) {
                int c = cb2 + nt * 8 + tig * 2;
                float v0 = acc[mt][nt][0], v1 = acc[mt][nt][1];
                float v2 = acc[mt][nt][2], v3 = acc[mt][nt][3];
                if (act) { v0 = elu1(v0); v1 = elu1(v1); v2 = elu1(v2); v3 = elu1(v3); }
                *(float2*)&dst[(size_t)r0 * 512 + c]       = make_float2(v0, v1);
                *(float2*)&dst[(size_t)(r0 + 8) * 512 + c] = make_float2(v2, v3);
            }
        }
    } else {
        const int cb2 = n0 + wn;
#pragma unroll
        for (int mt = 0; mt < 4; mt++) {
            int r0 = m0 + wm + mt * 16 + g;
#pragma unroll
            for (int nt = 0; nt < 4; nt++) {
                int c = cb2 + nt * 8 + tig * 2;
                float b0 = bias[c], b1 = bias[c + 1];
                *(float2*)&Out[(size_t)r0 * 512 + c] =
                    make_float2(acc[mt][nt][0] + b0, acc[mt][nt][1] + b1);
                *(float2*)&Out[(size_t)(r0 + 8) * 512 + c] =
                    make_float2(acc[mt][nt][2] + b0, acc[mt][nt][3] + b1);
            }
        }
    }
}

// ============================================================================
// kv partial reduce + combine (fp32 SIMT) [R1/R5-verified]
// ============================================================================
__global__ __launch_bounds__(256, 4) void kv_reduce()
{
    __shared__ float ks[8][64];
    __shared__ float vs[8][64];
    const int bh = blockIdx.x;
    const int b = bh >> 3, h = bh & 7;
    const int nbase = blockIdx.y * 512;
    const int tid = threadIdx.x;
    const int tx = tid & 15, ty = tid >> 4;

    float acc[4][4];
#pragma unroll
    for (int i = 0; i < 4; i++)
#pragma unroll
        for (int j = 0; j < 4; j++) acc[i][j] = 0.f;
    float ksacc[4] = {0.f, 0.f, 0.f, 0.f};

    const int lr = (tid & 127) >> 4;
    const int lc = tid & 15;
    const float* src = (tid < 128) ? g_k : g_v;
    float* sdst = (tid < 128) ? &ks[lr][lc * 4] : &vs[lr][lc * 4];

    for (int r0 = 0; r0 < 512; r0 += 8) {
        int n = nbase + r0 + lr;
        float4 val = *(const float4*)&src[((size_t)(b * 8192 + n)) * 512 + h * 64 + lc * 4];
        *(float4*)sdst = val;
        __syncthreads();
#pragma unroll
        for (int r = 0; r < 8; r++) {
            float kf[4], vf[4];
            *(float4*)kf = *(float4*)&ks[r][tx * 4];
            *(float4*)vf = *(float4*)&vs[r][ty * 4];
#pragma unroll
            for (int i = 0; i < 4; i++)
#pragma unroll
                for (int j = 0; j < 4; j++) acc[i][j] += kf[i] * vf[j];
            if (ty == 0) {
#pragma unroll
                for (int i = 0; i < 4; i++) ksacc[i] += kf[i];
            }
        }
        __syncthreads();
    }

    const size_t base = (size_t)(bh * 16 + blockIdx.y) * 4160;
#pragma unroll
    for (int i = 0; i < 4; i++)
#pragma unroll
        for (int j = 0; j < 4; j++)
            g_kvpart[base + (tx * 4 + i) * 64 + ty * 4 + j] = acc[i][j];
    if (ty == 0) {
#pragma unroll
        for (int i = 0; i < 4; i++) g_kvpart[base + 4096 + tx * 4 + i] = ksacc[i];
    }
}

__global__ void kv_combine()
{
    const int bh = blockIdx.x;
    const int i0 = blockIdx.y * 260;
    const int iend = (i0 + 260 < 4160) ? i0 + 260 : 4160;
    for (int i = i0 + threadIdx.x; i < iend; i += 256) {
        float s = 0.f;
#pragma unroll
        for (int c = 0; c < 16; c++) s += g_kvpart[(size_t)(bh * 16 + c) * 4160 + i];
        g_kv[(size_t)bh * 4160 + i] = s;
    }
}

// ============================================================================
// Wbig^T bf16 hi/lo  [R6-verified]
// ============================================================================
__global__ void make_wbig(const float* __restrict__ Wout)
{
    const int r = blockIdx.x;          // h*64+d
    const int b = blockIdx.y;
    const int h = r >> 6, d = r & 63;
    __shared__ float kvrow[64];
    if (threadIdx.x < 64)
        kvrow[threadIdx.x] = g_kv[(size_t)(b * 8 + h) * 4160 + d * 64 + threadIdx.x];
    __syncthreads();
    float acc[4] = {0.f, 0.f, 0.f, 0.f};
    for (int m = 0; m < 64; m++) {
        float kvv = kvrow[m];
        const float* wrow = Wout + (size_t)(h * 64 + m) * 512;
#pragma unroll
        for (int i = 0; i < 4; i++) acc[i] += kvv * wrow[threadIdx.x + i * 128];
    }
#pragma unroll
    for (int i = 0; i < 4; i++) {
        int j = threadIdx.x + i * 128;
        __nv_bfloat16 hi, lo;
        split2(acc[i], hi, lo);
        g_wbth[(size_t)b * 262144 + (size_t)j * 512 + r] = hi;
        g_wbtl[(size_t)b * 262144 + (size_t)j * 512 + r] = lo;
    }
}

// ============================================================================
extern "C" void kernel_launch(void* const* d_in, const int* in_sizes, int n_in,
                              void* d_out, int out_size)
{
    const float* x     = (const float*)d_in[0];   // [4,8192,512]
    const float* w_qkv = (const float*)d_in[1];   // [512,1536]
    const float* w_out = (const float*)d_in[2];   // [512,512]
    const float* b_out = (const float*)d_in[3];   // [512]
    float* out = (float*)d_out;                   // [4,8192,512]

    float* wt_p;    cudaGetSymbolAddress((void**)&wt_p,  g_wt);
    __nv_bfloat16 *xh_p, *xl_p, *wth_p, *wtl_p, *qzh_p, *qzl_p, *wbth_p, *wbtl_p;
    cudaGetSymbolAddress((void**)&xh_p,  g_xh);
    cudaGetSymbolAddress((void**)&xl_p,  g_xl);
    cudaGetSymbolAddress((void**)&wth_p, g_wth);
    cudaGetSymbolAddress((void**)&wtl_p, g_wtl);
    cudaGetSymbolAddress((void**)&qzh_p, g_qzh);
    cudaGetSymbolAddress((void**)&qzl_p, g_qzl);
    cudaGetSymbolAddress((void**)&wbth_p, g_wbth);
    cudaGetSymbolAddress((void**)&wbtl_p, g_wbtl);

    transpose_w<<<dim3(48, 16), dim3(32, 8)>>>(w_qkv);
    conv_split<<<16384, 256>>>(x, xh_p, xl_p);                 // X
    conv_split<<<768, 256>>>(wt_p, wth_p, wtl_p);              // W^T
    gemm_mma<0><<<dim3(12, 256), 256>>>(xh_p, xl_p, wth_p, wtl_p, nullptr, nullptr);
    kv_reduce<<<dim3(32, 16), 256>>>();
    kv_combine<<<dim3(32, 16), 256>>>();
    make_wbig<<<dim3(512, 4), 128>>>(w_out);
    z_split<<<32768, 128>>>();
    gemm_mma<1><<<dim3(4, 256), 256>>>(qzh_p, qzl_p, wbth_p, wbtl_p, b_out, out);
}